// round 9
// baseline (speedup 1.0000x reference)
#include <cuda_runtime.h>
#include <math.h>
#include <float.h>

#define NN 20000
#define EE 320000
#define EPSV 1e-16f
#define SCALE1 0.17677669529663687f   // 1/sqrt(32)

// ---------------- device scratch (static; no cudaMalloc) ------------------
__device__ float g_QKVS1[NN * 512];   // per node: [q(128)|k(128)|v(128)|s(128)]
__device__ float g_QKVS2[NN * 16];    // per node: [q(4)|kv interleaved(8)|s(4)]
__device__ int   g_deg[NN];
__device__ int   g_off[NN + 1];
__device__ int   g_pos[NN];
__device__ int   g_ssrc[EE];          // src sorted by dst (CSR payload)
__device__ float g_accum;
__device__ int   g_done;

// ---------------- f32x2 packed-FMA helpers --------------------------------
#define FMA2(d, a, b, c) \
    asm("fma.rn.f32x2 %0, %1, %2, %3;" : "=l"(d) : "l"(a), "l"(b), "l"(c))

__device__ __forceinline__ unsigned long long pack2(float lo, float hi) {
    unsigned long long o;
    asm("mov.b64 %0, {%1, %2};" : "=l"(o) : "r"(__float_as_uint(lo)), "r"(__float_as_uint(hi)));
    return o;
}
__device__ __forceinline__ float2 unpack2(unsigned long long v) {
    unsigned lo, hi;
    asm("mov.b64 {%0, %1}, %2;" : "=r"(lo), "=r"(hi) : "l"(v));
    return make_float2(__uint_as_float(lo), __uint_as_float(hi));
}
__device__ __forceinline__ float dot4(float4 a, float4 b) {
    return a.x * b.x + a.y * b.y + a.z * b.z + a.w * b.w;
}

// ---------------- init ----------------------------------------------------
__global__ void init_kernel() {
    int i = blockIdx.x * blockDim.x + threadIdx.x;
    if (i < NN) g_deg[i] = 0;
    if (i == 0) { g_accum = 0.0f; g_done = 0; }
}

// ---------------- CSR build (4 edges/thread for MLP) ----------------------
__global__ void hist_kernel(const int* __restrict__ dst) {
    int t = blockIdx.x * blockDim.x + threadIdx.x;
    int e = t * 4;
    if (e < EE) {
        int4 d4 = *(const int4*)&dst[e];
        atomicAdd(&g_deg[d4.x], 1);
        atomicAdd(&g_deg[d4.y], 1);
        atomicAdd(&g_deg[d4.z], 1);
        atomicAdd(&g_deg[d4.w], 1);
    }
}

// single-block exclusive scan over g_deg -> g_off, g_pos
__global__ void scan_kernel() {
    __shared__ int wsum[32];
    __shared__ int carry_sh;
    int tid = threadIdx.x;
    int lane = tid & 31, wid = tid >> 5;
    if (tid == 0) { carry_sh = 0; g_off[0] = 0; }
    __syncthreads();

    const int CHUNKS = (NN + 1023) / 1024;
    for (int c = 0; c < CHUNKS; c++) {
        int i = c * 1024 + tid;
        int v = (i < NN) ? g_deg[i] : 0;
        int base = carry_sh;
        int incl = v;
#pragma unroll
        for (int d = 1; d < 32; d <<= 1) {
            int t = __shfl_up_sync(0xffffffffu, incl, d);
            if (lane >= d) incl += t;
        }
        if (lane == 31) wsum[wid] = incl;
        __syncthreads();
        if (wid == 0) {
            int wi = wsum[lane];
#pragma unroll
            for (int d = 1; d < 32; d <<= 1) {
                int t = __shfl_up_sync(0xffffffffu, wi, d);
                if (lane >= d) wi += t;
            }
            wsum[lane] = wi;
        }
        __syncthreads();
        int wexcl = (wid == 0) ? 0 : wsum[wid - 1];
        int total = wsum[31];
        int my_incl = base + wexcl + incl;
        if (i < NN) {
            g_off[i + 1] = my_incl;
            g_pos[i] = my_incl - v;
        }
        __syncthreads();
        if (tid == 0) carry_sh = base + total;
        __syncthreads();
    }
}

__global__ void scatter_kernel(const int* __restrict__ src, const int* __restrict__ dst) {
    int t = blockIdx.x * blockDim.x + threadIdx.x;
    int e = t * 4;
    if (e >= EE) return;
    int4 d4 = *(const int4*)&dst[e];
    int4 s4 = *(const int4*)&src[e];
    int p0 = atomicAdd(&g_pos[d4.x], 1);
    int p1 = atomicAdd(&g_pos[d4.y], 1);
    int p2 = atomicAdd(&g_pos[d4.z], 1);
    int p3 = atomicAdd(&g_pos[d4.w], 1);
    g_ssrc[p0] = s4.x;
    g_ssrc[p1] = s4.y;
    g_ssrc[p2] = s4.z;
    g_ssrc[p3] = s4.w;
}

// ---------------- layer-1 fused QKVS GEMM (f32x2, MOV-free inner loop) ----
__global__ __launch_bounds__(256) void gemm1_kernel(
        const float* __restrict__ x,
        const float* __restrict__ Wq, const float* __restrict__ bq,
        const float* __restrict__ Wk, const float* __restrict__ bk,
        const float* __restrict__ Wv, const float* __restrict__ bv,
        const float* __restrict__ Ws, const float* __restrict__ bs) {
    __shared__ unsigned long long As2[16][128];   // (a,a) packed, [k][row]
    __shared__ float Bs[16][128];                 // [k][col]

    int tid = threadIdx.x;
    int tx = tid & 15;
    int ty = tid >> 4;
    int row0 = blockIdx.x * 128;
    int m = blockIdx.y;

    const float* W = (m == 0) ? Wq : (m == 1) ? Wk : (m == 2) ? Wv : Ws;
    const float* B = (m == 0) ? bq : (m == 1) ? bk : (m == 2) ? bv : bs;

    unsigned long long acc[8][4];
#pragma unroll
    for (int i = 0; i < 8; i++)
#pragma unroll
        for (int j = 0; j < 4; j++) acc[i][j] = 0ull;

    int arow = tid & 127;
    int akq  = (tid >> 7) * 8;
    int bcol = (tid & 31) * 4;
    int bkr  = tid >> 5;

    for (int kt = 0; kt < 8; kt++) {
        int k0 = kt * 16;
        int gr = row0 + arow;
        float4 xa = make_float4(0.f, 0.f, 0.f, 0.f);
        float4 xb = make_float4(0.f, 0.f, 0.f, 0.f);
        if (gr < NN) {
            xa = *(const float4*)&x[gr * 128 + k0 + akq];
            xb = *(const float4*)&x[gr * 128 + k0 + akq + 4];
        }
        As2[akq + 0][arow] = pack2(xa.x, xa.x);
        As2[akq + 1][arow] = pack2(xa.y, xa.y);
        As2[akq + 2][arow] = pack2(xa.z, xa.z);
        As2[akq + 3][arow] = pack2(xa.w, xa.w);
        As2[akq + 4][arow] = pack2(xb.x, xb.x);
        As2[akq + 5][arow] = pack2(xb.y, xb.y);
        As2[akq + 6][arow] = pack2(xb.z, xb.z);
        As2[akq + 7][arow] = pack2(xb.w, xb.w);
        *(float4*)&Bs[bkr][bcol]     = *(const float4*)&W[(k0 + bkr) * 128 + bcol];
        *(float4*)&Bs[bkr + 8][bcol] = *(const float4*)&W[(k0 + bkr + 8) * 128 + bcol];
        __syncthreads();

#pragma unroll
        for (int kk = 0; kk < 16; kk++) {
            ulonglong2 b01 = *(ulonglong2*)&Bs[kk][tx * 8];
            ulonglong2 b23 = *(ulonglong2*)&Bs[kk][tx * 8 + 4];
#pragma unroll
            for (int i = 0; i < 8; i++) {
                unsigned long long a = As2[kk][ty * 8 + i];
                FMA2(acc[i][0], a, b01.x, acc[i][0]);
                FMA2(acc[i][1], a, b01.y, acc[i][1]);
                FMA2(acc[i][2], a, b23.x, acc[i][2]);
                FMA2(acc[i][3], a, b23.y, acc[i][3]);
            }
        }
        __syncthreads();
    }

    float4 bb0 = *(const float4*)&B[tx * 8];
    float4 bb1 = *(const float4*)&B[tx * 8 + 4];
#pragma unroll
    for (int i = 0; i < 8; i++) {
        int gr = row0 + ty * 8 + i;
        if (gr < NN) {
            float2 p0 = unpack2(acc[i][0]);
            float2 p1 = unpack2(acc[i][1]);
            float2 p2 = unpack2(acc[i][2]);
            float2 p3 = unpack2(acc[i][3]);
            float4 o0 = make_float4(p0.x + bb0.x, p0.y + bb0.y, p1.x + bb0.z, p1.y + bb0.w);
            float4 o1 = make_float4(p2.x + bb1.x, p2.y + bb1.y, p3.x + bb1.z, p3.y + bb1.w);
            *(float4*)&g_QKVS1[gr * 512 + m * 128 + tx * 8]     = o0;
            *(float4*)&g_QKVS1[gr * 512 + m * 128 + tx * 8 + 4] = o1;
        }
    }
}

// ---------------- layer-1 fused edge phase + gemm2 ------------------------
// TWO warps per node (warp pair p=0/1), each warp's halves take edges
// i = 4j + 2p + half; all warps run steps = ceil(deg/4) predicated
// iterations so every shfl is fully converged. Pair combined via smem.
__global__ __launch_bounds__(256) void edge1_fused(
        const float* __restrict__ W2q, const float* __restrict__ b2q,
        const float* __restrict__ W2k, const float* __restrict__ b2k,
        const float* __restrict__ W2v, const float* __restrict__ b2v,
        const float* __restrict__ W2s, const float* __restrict__ b2s) {
    __shared__ float Wsm[16][128];    // [out j][in i], j = m*4+c
    __shared__ float bsm[16];
    __shared__ float comb[4][16][9];  // [node-in-block][l][se|aca|acb]

    int tid = threadIdx.x;
    for (int f = tid; f < 2048; f += 256) {
        int j = f >> 7, i = f & 127;
        int mm = j >> 2, c = j & 3;
        const float* Wm = (mm == 0) ? W2q : (mm == 1) ? W2k : (mm == 2) ? W2v : W2s;
        Wsm[j][i] = Wm[i * 4 + c];
    }
    if (tid < 16) {
        int mm = tid >> 2, c = tid & 3;
        const float* bm = (mm == 0) ? b2q : (mm == 1) ? b2k : (mm == 2) ? b2v : b2s;
        bsm[tid] = bm[c];
    }
    __syncthreads();

    int wid = tid >> 5, lane = tid & 31;
    int half = lane >> 4;          // 0/1 within warp
    int p = wid & 1;               // warp-pair index
    int nb = wid >> 1;             // node-in-block 0..3
    int l = lane & 15;             // channel group: floats [8l, 8l+8)
    int n = blockIdx.x * 4 + nb;   // 5000*4 = 20000 exactly

    int off = g_off[n];
    int deg = g_off[n + 1] - off;
    int steps = (deg + 3) >> 2;    // identical for all 4 slices

    const float* base1 = &g_QKVS1[(size_t)n * 512 + l * 8];
    float4 qa = *(const float4*)(base1);
    float4 qb = *(const float4*)(base1 + 4);

    float se = 0.0f;
    float4 aca = make_float4(0.f, 0.f, 0.f, 0.f);
    float4 acb = make_float4(0.f, 0.f, 0.f, 0.f);

    int slice = 2 * p + half;      // 0..3
    int j = 0;
    for (; j + 2 <= steps; j += 2) {
        int i0 = 4 * j + slice;
        int i1 = i0 + 4;
        bool ok0 = i0 < deg;
        bool ok1 = i1 < deg;
        int s0 = g_ssrc[off + (ok0 ? i0 : 0)];
        int s1 = g_ssrc[off + (ok1 ? i1 : 0)];
        const float* p0 = &g_QKVS1[(size_t)s0 * 512 + 128 + l * 8];
        const float* p1 = &g_QKVS1[(size_t)s1 * 512 + 128 + l * 8];
        float4 k0a = *(const float4*)(p0);
        float4 k0b = *(const float4*)(p0 + 4);
        float4 k1a = *(const float4*)(p1);
        float4 k1b = *(const float4*)(p1 + 4);
        float4 v0a = *(const float4*)(p0 + 128);
        float4 v0b = *(const float4*)(p0 + 132);
        float4 v1a = *(const float4*)(p1 + 128);
        float4 v1b = *(const float4*)(p1 + 132);
        float d0 = dot4(qa, k0a) + dot4(qb, k0b);
        float d1 = dot4(qa, k1a) + dot4(qb, k1b);
        d0 += __shfl_xor_sync(0xffffffffu, d0, 1, 4);
        d1 += __shfl_xor_sync(0xffffffffu, d1, 1, 4);
        d0 += __shfl_xor_sync(0xffffffffu, d0, 2, 4);
        d1 += __shfl_xor_sync(0xffffffffu, d1, 2, 4);
        float e0 = ok0 ? __expf(d0 * SCALE1) : 0.0f;
        float e1 = ok1 ? __expf(d1 * SCALE1) : 0.0f;
        se += e0 + e1;
        aca.x += e0 * v0a.x + e1 * v1a.x;
        aca.y += e0 * v0a.y + e1 * v1a.y;
        aca.z += e0 * v0a.z + e1 * v1a.z;
        aca.w += e0 * v0a.w + e1 * v1a.w;
        acb.x += e0 * v0b.x + e1 * v1b.x;
        acb.y += e0 * v0b.y + e1 * v1b.y;
        acb.z += e0 * v0b.z + e1 * v1b.z;
        acb.w += e0 * v0b.w + e1 * v1b.w;
    }
    if (j < steps) {
        int i0 = 4 * j + slice;
        bool ok0 = i0 < deg;
        int s = g_ssrc[off + (ok0 ? i0 : 0)];
        const float* pp = &g_QKVS1[(size_t)s * 512 + 128 + l * 8];
        float4 ka = *(const float4*)(pp);
        float4 kb = *(const float4*)(pp + 4);
        float4 va = *(const float4*)(pp + 128);
        float4 vb = *(const float4*)(pp + 132);
        float d = dot4(qa, ka) + dot4(qb, kb);
        d += __shfl_xor_sync(0xffffffffu, d, 1, 4);
        d += __shfl_xor_sync(0xffffffffu, d, 2, 4);
        float e = ok0 ? __expf(d * SCALE1) : 0.0f;
        se += e;
        aca.x += e * va.x; aca.y += e * va.y; aca.z += e * va.z; aca.w += e * va.w;
        acb.x += e * vb.x; acb.y += e * vb.y; acb.z += e * vb.z; acb.w += e * vb.w;
    }

    // cross-half combine within warp (disjoint edge sets)
    se += __shfl_xor_sync(0xffffffffu, se, 16);
    aca.x += __shfl_xor_sync(0xffffffffu, aca.x, 16);
    aca.y += __shfl_xor_sync(0xffffffffu, aca.y, 16);
    aca.z += __shfl_xor_sync(0xffffffffu, aca.z, 16);
    aca.w += __shfl_xor_sync(0xffffffffu, aca.w, 16);
    acb.x += __shfl_xor_sync(0xffffffffu, acb.x, 16);
    acb.y += __shfl_xor_sync(0xffffffffu, acb.y, 16);
    acb.z += __shfl_xor_sync(0xffffffffu, acb.z, 16);
    acb.w += __shfl_xor_sync(0xffffffffu, acb.w, 16);

    // cross-warp combine: odd warp publishes, even warp accumulates
    if (p == 1 && half == 0) {
        float* cc = &comb[nb][l][0];
        cc[0] = se;
        cc[1] = aca.x; cc[2] = aca.y; cc[3] = aca.z; cc[4] = aca.w;
        cc[5] = acb.x; cc[6] = acb.y; cc[7] = acb.z; cc[8] = acb.w;
    }
    __syncthreads();
    if (p == 1) return;   // odd warp done

    {
        const float* cc = &comb[nb][l][0];
        se += cc[0];
        aca.x += cc[1]; aca.y += cc[2]; aca.z += cc[3]; aca.w += cc[4];
        acb.x += cc[5]; acb.y += cc[6]; acb.z += cc[7]; acb.w += cc[8];
    }

    float inv = 1.0f / (se + EPSV);
    float4 ska = *(const float4*)(base1 + 384);
    float4 skb = *(const float4*)(base1 + 388);
    float4 h1a, h1b;
    h1a.x = fmaxf(aca.x * inv + ska.x, 0.0f);
    h1a.y = fmaxf(aca.y * inv + ska.y, 0.0f);
    h1a.z = fmaxf(aca.z * inv + ska.z, 0.0f);
    h1a.w = fmaxf(aca.w * inv + ska.w, 0.0f);
    h1b.x = fmaxf(acb.x * inv + skb.x, 0.0f);
    h1b.y = fmaxf(acb.y * inv + skb.y, 0.0f);
    h1b.z = fmaxf(acb.z * inv + skb.z, 0.0f);
    h1b.w = fmaxf(acb.w * inv + skb.w, 0.0f);

    // gemm2 on even warp: half0 computes outputs j=0..7, half1 j=8..15
    int jbase = half * 8;
    float part[8];
#pragma unroll
    for (int jj = 0; jj < 8; jj++) {
        int jo = jbase + jj;
        float4 w0 = *(float4*)&Wsm[jo][l * 8];
        float4 w1 = *(float4*)&Wsm[jo][l * 8 + 4];
        float pv = dot4(h1a, w0) + dot4(h1b, w1);
#pragma unroll
        for (int d = 8; d > 0; d >>= 1)
            pv += __shfl_xor_sync(0xffffffffu, pv, d, 16);
        part[jj] = pv;
    }
    if (l == 0) {
        // output layout: [q(4) | kv interleaved(8) | s(4)]
        float* o = &g_QKVS2[n * 16];
        if (half == 0) {
#pragma unroll
            for (int c = 0; c < 4; c++) {
                o[c] = part[c] + bsm[c];                    // q
                o[4 + 2 * c] = part[4 + c] + bsm[4 + c];    // k
            }
        } else {
#pragma unroll
            for (int c = 0; c < 4; c++) {
                o[5 + 2 * c] = part[c] + bsm[8 + c];        // v
                o[12 + c]    = part[4 + c] + bsm[12 + c];   // s
            }
        }
    }
}

// ---------------- layer-2 edge phase + final linear + mean (one kernel) ---
__global__ __launch_bounds__(256) void edge2_fused(
        const float* __restrict__ Wl, const float* __restrict__ bl,
        float* __restrict__ out) {
    __shared__ float ysm[8];
    int tid = threadIdx.x;
    int t = blockIdx.x * 256 + tid;
    int n = t >> 2, h = t & 3;

    float y = 0.0f;
    if (n < NN) {
        int off = g_off[n], end = g_off[n + 1];
        float qh = g_QKVS2[n * 16 + h];
        float s = 0.0f, a = 0.0f;
        int i = off;
        for (; i + 4 <= end; i += 4) {
            int s0 = g_ssrc[i], s1 = g_ssrc[i + 1], s2 = g_ssrc[i + 2], s3 = g_ssrc[i + 3];
            float2 kv0 = *(const float2*)&g_QKVS2[s0 * 16 + 4 + 2 * h];
            float2 kv1 = *(const float2*)&g_QKVS2[s1 * 16 + 4 + 2 * h];
            float2 kv2 = *(const float2*)&g_QKVS2[s2 * 16 + 4 + 2 * h];
            float2 kv3 = *(const float2*)&g_QKVS2[s3 * 16 + 4 + 2 * h];
            float e0 = __expf(qh * kv0.x);
            float e1 = __expf(qh * kv1.x);
            float e2 = __expf(qh * kv2.x);
            float e3 = __expf(qh * kv3.x);
            s += (e0 + e1) + (e2 + e3);
            a += e0 * kv0.y + e1 * kv1.y + e2 * kv2.y + e3 * kv3.y;
        }
        for (; i < end; i++) {
            int sn = g_ssrc[i];
            float2 kv = *(const float2*)&g_QKVS2[sn * 16 + 4 + 2 * h];
            float e = __expf(qh * kv.x);
            s += e;
            a += e * kv.y;
        }
        float o = a / (s + EPSV) + g_QKVS2[n * 16 + 12 + h];
        y = o * Wl[h];
    }

#pragma unroll
    for (int d = 16; d > 0; d >>= 1) y += __shfl_xor_sync(0xffffffffu, y, d);
    if ((tid & 31) == 0) ysm[tid >> 5] = y;
    __syncthreads();
    if (tid == 0) {
        float tsum = 0.f;
#pragma unroll
        for (int w = 0; w < 8; w++) tsum += ysm[w];
        atomicAdd(&g_accum, tsum);
        __threadfence();
        int ticket = atomicAdd(&g_done, 1);
        if (ticket == (int)gridDim.x - 1) {
            out[0] = g_accum * (1.0f / (float)NN) + bl[0];
        }
    }
}

// ---------------- launch --------------------------------------------------
extern "C" void kernel_launch(void* const* d_in, const int* in_sizes, int n_in,
                              void* d_out, int out_size) {
    const float* x    = (const float*)d_in[0];
    const int*   esrc = (const int*)d_in[1];
    const int*   edst = (const int*)d_in[2];
    const float* W1q = (const float*)d_in[3];  const float* b1q = (const float*)d_in[4];
    const float* W1k = (const float*)d_in[5];  const float* b1k = (const float*)d_in[6];
    const float* W1v = (const float*)d_in[7];  const float* b1v = (const float*)d_in[8];
    const float* W1s = (const float*)d_in[9];  const float* b1s = (const float*)d_in[10];
    const float* W2q = (const float*)d_in[11]; const float* b2q = (const float*)d_in[12];
    const float* W2k = (const float*)d_in[13]; const float* b2k = (const float*)d_in[14];
    const float* W2v = (const float*)d_in[15]; const float* b2v = (const float*)d_in[16];
    const float* W2s = (const float*)d_in[17]; const float* b2s = (const float*)d_in[18];
    const float* Wl  = (const float*)d_in[19]; const float* bl  = (const float*)d_in[20];
    float* out = (float*)d_out;

    // one-time creation of side stream + events (not device memory)
    static cudaStream_t sB = nullptr;
    static cudaEvent_t evFork = nullptr, evJoin = nullptr;
    if (!sB) {
        cudaStreamCreateWithFlags(&sB, cudaStreamNonBlocking);
        cudaEventCreateWithFlags(&evFork, cudaEventDisableTiming);
        cudaEventCreateWithFlags(&evJoin, cudaEventDisableTiming);
    }

    // fork: CSR build on sB, overlapped with gemm1 on the main stream
    cudaEventRecord(evFork, 0);
    cudaStreamWaitEvent(sB, evFork, 0);

    init_kernel<<<(NN + 255) / 256, 256, 0, sB>>>();
    hist_kernel<<<(EE / 4 + 255) / 256, 256, 0, sB>>>(edst);
    scan_kernel<<<1, 1024, 0, sB>>>();
    scatter_kernel<<<(EE / 4 + 255) / 256, 256, 0, sB>>>(esrc, edst);
    cudaEventRecord(evJoin, sB);

    dim3 g1((NN + 127) / 128, 4);
    gemm1_kernel<<<g1, 256>>>(x, W1q, b1q, W1k, b1k, W1v, b1v, W1s, b1s);

    // join: edge phase needs both gemm1 (main) and CSR (sB)
    cudaStreamWaitEvent(0, evJoin, 0);

    edge1_fused<<<NN / 4, 256>>>(W2q, b2q, W2k, b2k, W2v, b2v, W2s, b2s);
    edge2_fused<<<(NN * 4 + 255) / 256, 256>>>(Wl, bl, out);
}

// round 12
// speedup vs baseline: 1.1501x; 1.1501x over previous
#include <cuda_runtime.h>
#include <cuda_bf16.h>
#include <cstdint>
#include <math.h>
#include <float.h>

#define NN 20000
#define EE 320000
#define EPSV 1e-16f
#define SCALE1 0.17677669529663687f   // 1/sqrt(32)

// ---------------- device scratch (static; no cudaMalloc) ------------------
__device__ float g_QKVS1[NN * 512];   // per node: [q(128)|k(128)|v(128)|s(128)] fp32
__device__ __nv_bfloat16 g_KV16[NN * 256]; // per node: [k(128)|v(128)] bf16
__device__ float g_QKVS2[NN * 16];    // per node: [q(4)|kv interleaved(8)|s(4)]
__device__ int   g_deg[NN];
__device__ int   g_off[NN + 1];
__device__ int   g_pos[NN];
__device__ int   g_ssrc[EE];          // src sorted by dst (CSR payload)
__device__ float g_accum;
__device__ int   g_done;

// ---------------- f32x2 packed-FMA helpers --------------------------------
#define FMA2(d, a, b, c) \
    asm("fma.rn.f32x2 %0, %1, %2, %3;" : "=l"(d) : "l"(a), "l"(b), "l"(c))

__device__ __forceinline__ unsigned long long pack2(float lo, float hi) {
    unsigned long long o;
    asm("mov.b64 %0, {%1, %2};" : "=l"(o) : "r"(__float_as_uint(lo)), "r"(__float_as_uint(hi)));
    return o;
}
__device__ __forceinline__ float2 unpack2(unsigned long long v) {
    unsigned lo, hi;
    asm("mov.b64 {%0, %1}, %2;" : "=r"(lo), "=r"(hi) : "l"(v));
    return make_float2(__uint_as_float(lo), __uint_as_float(hi));
}
__device__ __forceinline__ float dot4(float4 a, float4 b) {
    return a.x * b.x + a.y * b.y + a.z * b.z + a.w * b.w;
}
// load 8 bf16 (16B) -> two float4
__device__ __forceinline__ void ld_bf8(const __nv_bfloat16* p, float4& a, float4& b) {
    uint4 r = *(const uint4*)p;
    float2 f0 = __bfloat1622float2(*(__nv_bfloat162*)&r.x);
    float2 f1 = __bfloat1622float2(*(__nv_bfloat162*)&r.y);
    float2 f2 = __bfloat1622float2(*(__nv_bfloat162*)&r.z);
    float2 f3 = __bfloat1622float2(*(__nv_bfloat162*)&r.w);
    a = make_float4(f0.x, f0.y, f1.x, f1.y);
    b = make_float4(f2.x, f2.y, f3.x, f3.y);
}

// ---------------- init ----------------------------------------------------
__global__ void init_kernel() {
    int i = blockIdx.x * blockDim.x + threadIdx.x;
    if (i < NN) g_deg[i] = 0;
    if (i == 0) { g_accum = 0.0f; g_done = 0; }
}

// ---------------- CSR build (4 edges/thread for MLP) ----------------------
__global__ void hist_kernel(const int* __restrict__ dst) {
    int t = blockIdx.x * blockDim.x + threadIdx.x;
    int e = t * 4;
    if (e < EE) {
        int4 d4 = *(const int4*)&dst[e];
        atomicAdd(&g_deg[d4.x], 1);
        atomicAdd(&g_deg[d4.y], 1);
        atomicAdd(&g_deg[d4.z], 1);
        atomicAdd(&g_deg[d4.w], 1);
    }
}

__global__ void scan_kernel() {
    __shared__ int wsum[32];
    __shared__ int carry_sh;
    int tid = threadIdx.x;
    int lane = tid & 31, wid = tid >> 5;
    if (tid == 0) { carry_sh = 0; g_off[0] = 0; }
    __syncthreads();

    const int CHUNKS = (NN + 1023) / 1024;
    for (int c = 0; c < CHUNKS; c++) {
        int i = c * 1024 + tid;
        int v = (i < NN) ? g_deg[i] : 0;
        int base = carry_sh;
        int incl = v;
#pragma unroll
        for (int d = 1; d < 32; d <<= 1) {
            int t = __shfl_up_sync(0xffffffffu, incl, d);
            if (lane >= d) incl += t;
        }
        if (lane == 31) wsum[wid] = incl;
        __syncthreads();
        if (wid == 0) {
            int wi = wsum[lane];
#pragma unroll
            for (int d = 1; d < 32; d <<= 1) {
                int t = __shfl_up_sync(0xffffffffu, wi, d);
                if (lane >= d) wi += t;
            }
            wsum[lane] = wi;
        }
        __syncthreads();
        int wexcl = (wid == 0) ? 0 : wsum[wid - 1];
        int total = wsum[31];
        int my_incl = base + wexcl + incl;
        if (i < NN) {
            g_off[i + 1] = my_incl;
            g_pos[i] = my_incl - v;
        }
        __syncthreads();
        if (tid == 0) carry_sh = base + total;
        __syncthreads();
    }
}

__global__ void scatter_kernel(const int* __restrict__ src, const int* __restrict__ dst) {
    int t = blockIdx.x * blockDim.x + threadIdx.x;
    int e = t * 4;
    if (e >= EE) return;
    int4 d4 = *(const int4*)&dst[e];
    int4 s4 = *(const int4*)&src[e];
    int p0 = atomicAdd(&g_pos[d4.x], 1);
    int p1 = atomicAdd(&g_pos[d4.y], 1);
    int p2 = atomicAdd(&g_pos[d4.z], 1);
    int p3 = atomicAdd(&g_pos[d4.w], 1);
    g_ssrc[p0] = s4.x;
    g_ssrc[p1] = s4.y;
    g_ssrc[p2] = s4.z;
    g_ssrc[p3] = s4.w;
}

// ---------------- layer-1 fused QKVS GEMM (f32x2, MOV-free inner loop) ----
// Also emits bf16 copies of k (m=1) and v (m=2) into g_KV16.
__global__ __launch_bounds__(256) void gemm1_kernel(
        const float* __restrict__ x,
        const float* __restrict__ Wq, const float* __restrict__ bq,
        const float* __restrict__ Wk, const float* __restrict__ bk,
        const float* __restrict__ Wv, const float* __restrict__ bv,
        const float* __restrict__ Ws, const float* __restrict__ bs) {
    __shared__ unsigned long long As2[16][128];   // (a,a) packed, [k][row]
    __shared__ float Bs[16][128];                 // [k][col]

    int tid = threadIdx.x;
    int tx = tid & 15;
    int ty = tid >> 4;
    int row0 = blockIdx.x * 128;
    int m = blockIdx.y;

    const float* W = (m == 0) ? Wq : (m == 1) ? Wk : (m == 2) ? Wv : Ws;
    const float* B = (m == 0) ? bq : (m == 1) ? bk : (m == 2) ? bv : bs;

    unsigned long long acc[8][4];
#pragma unroll
    for (int i = 0; i < 8; i++)
#pragma unroll
        for (int j = 0; j < 4; j++) acc[i][j] = 0ull;

    int arow = tid & 127;
    int akq  = (tid >> 7) * 8;
    int bcol = (tid & 31) * 4;
    int bkr  = tid >> 5;

    for (int kt = 0; kt < 8; kt++) {
        int k0 = kt * 16;
        int gr = row0 + arow;
        float4 xa = make_float4(0.f, 0.f, 0.f, 0.f);
        float4 xb = make_float4(0.f, 0.f, 0.f, 0.f);
        if (gr < NN) {
            xa = *(const float4*)&x[gr * 128 + k0 + akq];
            xb = *(const float4*)&x[gr * 128 + k0 + akq + 4];
        }
        As2[akq + 0][arow] = pack2(xa.x, xa.x);
        As2[akq + 1][arow] = pack2(xa.y, xa.y);
        As2[akq + 2][arow] = pack2(xa.z, xa.z);
        As2[akq + 3][arow] = pack2(xa.w, xa.w);
        As2[akq + 4][arow] = pack2(xb.x, xb.x);
        As2[akq + 5][arow] = pack2(xb.y, xb.y);
        As2[akq + 6][arow] = pack2(xb.z, xb.z);
        As2[akq + 7][arow] = pack2(xb.w, xb.w);
        *(float4*)&Bs[bkr][bcol]     = *(const float4*)&W[(k0 + bkr) * 128 + bcol];
        *(float4*)&Bs[bkr + 8][bcol] = *(const float4*)&W[(k0 + bkr + 8) * 128 + bcol];
        __syncthreads();

#pragma unroll
        for (int kk = 0; kk < 16; kk++) {
            ulonglong2 b01 = *(ulonglong2*)&Bs[kk][tx * 8];
            ulonglong2 b23 = *(ulonglong2*)&Bs[kk][tx * 8 + 4];
#pragma unroll
            for (int i = 0; i < 8; i++) {
                unsigned long long a = As2[kk][ty * 8 + i];
                FMA2(acc[i][0], a, b01.x, acc[i][0]);
                FMA2(acc[i][1], a, b01.y, acc[i][1]);
                FMA2(acc[i][2], a, b23.x, acc[i][2]);
                FMA2(acc[i][3], a, b23.y, acc[i][3]);
            }
        }
        __syncthreads();
    }

    float4 bb0 = *(const float4*)&B[tx * 8];
    float4 bb1 = *(const float4*)&B[tx * 8 + 4];
#pragma unroll
    for (int i = 0; i < 8; i++) {
        int gr = row0 + ty * 8 + i;
        if (gr < NN) {
            float2 p0 = unpack2(acc[i][0]);
            float2 p1 = unpack2(acc[i][1]);
            float2 p2 = unpack2(acc[i][2]);
            float2 p3 = unpack2(acc[i][3]);
            float4 o0 = make_float4(p0.x + bb0.x, p0.y + bb0.y, p1.x + bb0.z, p1.y + bb0.w);
            float4 o1 = make_float4(p2.x + bb1.x, p2.y + bb1.y, p3.x + bb1.z, p3.y + bb1.w);
            *(float4*)&g_QKVS1[gr * 512 + m * 128 + tx * 8]     = o0;
            *(float4*)&g_QKVS1[gr * 512 + m * 128 + tx * 8 + 4] = o1;
            if (m == 1 || m == 2) {
                __nv_bfloat162 hh[4];
                hh[0] = __floats2bfloat162_rn(o0.x, o0.y);
                hh[1] = __floats2bfloat162_rn(o0.z, o0.w);
                hh[2] = __floats2bfloat162_rn(o1.x, o1.y);
                hh[3] = __floats2bfloat162_rn(o1.z, o1.w);
                *(uint4*)&g_KV16[gr * 256 + (m - 1) * 128 + tx * 8] = *(uint4*)hh;
            }
        }
    }
}

// ---------------- layer-1 fused edge phase + gemm2 (single pass) ----------
// warp per dst node; 16 lanes per edge; bf16 k/v gathers (16B each).
__global__ __launch_bounds__(256) void edge1_fused(
        const float* __restrict__ W2q, const float* __restrict__ b2q,
        const float* __restrict__ W2k, const float* __restrict__ b2k,
        const float* __restrict__ W2v, const float* __restrict__ b2v,
        const float* __restrict__ W2s, const float* __restrict__ b2s) {
    __shared__ float Wsm[16][128];    // [out j][in i], j = m*4+c
    __shared__ float bsm[16];

    int tid = threadIdx.x;
    for (int f = tid; f < 2048; f += 256) {
        int j = f >> 7, i = f & 127;
        int mm = j >> 2, c = j & 3;
        const float* Wm = (mm == 0) ? W2q : (mm == 1) ? W2k : (mm == 2) ? W2v : W2s;
        Wsm[j][i] = Wm[i * 4 + c];
    }
    if (tid < 16) {
        int mm = tid >> 2, c = tid & 3;
        const float* bm = (mm == 0) ? b2q : (mm == 1) ? b2k : (mm == 2) ? b2v : b2s;
        bsm[tid] = bm[c];
    }
    __syncthreads();

    int wid = tid >> 5, lane = tid & 31;
    int half = lane >> 4;
    int l = lane & 15;
    int n = blockIdx.x * 8 + wid;

    int off = g_off[n];
    int deg = g_off[n + 1] - off;
    int steps = (deg + 1) >> 1;

    const float* base1 = &g_QKVS1[(size_t)n * 512 + l * 8];
    float4 qa = *(const float4*)(base1);
    float4 qb = *(const float4*)(base1 + 4);

    float se = 0.0f;
    float4 aca = make_float4(0.f, 0.f, 0.f, 0.f);
    float4 acb = make_float4(0.f, 0.f, 0.f, 0.f);

    int j = 0;
    for (; j + 2 <= steps; j += 2) {
        int i0 = 2 * j + half;
        int i1 = i0 + 2;
        bool ok0 = i0 < deg;
        bool ok1 = i1 < deg;
        int s0 = g_ssrc[off + (ok0 ? i0 : 0)];
        int s1 = g_ssrc[off + (ok1 ? i1 : 0)];
        const __nv_bfloat16* p0 = &g_KV16[(size_t)s0 * 256 + l * 8];
        const __nv_bfloat16* p1 = &g_KV16[(size_t)s1 * 256 + l * 8];
        float4 k0a, k0b, k1a, k1b, v0a, v0b, v1a, v1b;
        ld_bf8(p0, k0a, k0b);
        ld_bf8(p1, k1a, k1b);
        ld_bf8(p0 + 128, v0a, v0b);
        ld_bf8(p1 + 128, v1a, v1b);
        float d0 = dot4(qa, k0a) + dot4(qb, k0b);
        float d1 = dot4(qa, k1a) + dot4(qb, k1b);
        d0 += __shfl_xor_sync(0xffffffffu, d0, 1, 4);
        d1 += __shfl_xor_sync(0xffffffffu, d1, 1, 4);
        d0 += __shfl_xor_sync(0xffffffffu, d0, 2, 4);
        d1 += __shfl_xor_sync(0xffffffffu, d1, 2, 4);
        float e0 = ok0 ? __expf(d0 * SCALE1) : 0.0f;
        float e1 = ok1 ? __expf(d1 * SCALE1) : 0.0f;
        se += e0 + e1;
        aca.x += e0 * v0a.x + e1 * v1a.x;
        aca.y += e0 * v0a.y + e1 * v1a.y;
        aca.z += e0 * v0a.z + e1 * v1a.z;
        aca.w += e0 * v0a.w + e1 * v1a.w;
        acb.x += e0 * v0b.x + e1 * v1b.x;
        acb.y += e0 * v0b.y + e1 * v1b.y;
        acb.z += e0 * v0b.z + e1 * v1b.z;
        acb.w += e0 * v0b.w + e1 * v1b.w;
    }
    if (j < steps) {
        int i0 = 2 * j + half;
        bool ok0 = i0 < deg;
        int s = g_ssrc[off + (ok0 ? i0 : 0)];
        const __nv_bfloat16* p = &g_KV16[(size_t)s * 256 + l * 8];
        float4 ka, kb, va, vb;
        ld_bf8(p, ka, kb);
        ld_bf8(p + 128, va, vb);
        float d = dot4(qa, ka) + dot4(qb, kb);
        d += __shfl_xor_sync(0xffffffffu, d, 1, 4);
        d += __shfl_xor_sync(0xffffffffu, d, 2, 4);
        float e = ok0 ? __expf(d * SCALE1) : 0.0f;
        se += e;
        aca.x += e * va.x; aca.y += e * va.y; aca.z += e * va.z; aca.w += e * va.w;
        acb.x += e * vb.x; acb.y += e * vb.y; acb.z += e * vb.z; acb.w += e * vb.w;
    }

    // cross-half combine (halves processed disjoint edge sets)
    se += __shfl_xor_sync(0xffffffffu, se, 16);
    aca.x += __shfl_xor_sync(0xffffffffu, aca.x, 16);
    aca.y += __shfl_xor_sync(0xffffffffu, aca.y, 16);
    aca.z += __shfl_xor_sync(0xffffffffu, aca.z, 16);
    aca.w += __shfl_xor_sync(0xffffffffu, aca.w, 16);
    acb.x += __shfl_xor_sync(0xffffffffu, acb.x, 16);
    acb.y += __shfl_xor_sync(0xffffffffu, acb.y, 16);
    acb.z += __shfl_xor_sync(0xffffffffu, acb.z, 16);
    acb.w += __shfl_xor_sync(0xffffffffu, acb.w, 16);

    float inv = 1.0f / (se + EPSV);
    float4 ska = *(const float4*)(base1 + 384);
    float4 skb = *(const float4*)(base1 + 388);
    float4 h1a, h1b;
    h1a.x = fmaxf(aca.x * inv + ska.x, 0.0f);
    h1a.y = fmaxf(aca.y * inv + ska.y, 0.0f);
    h1a.z = fmaxf(aca.z * inv + ska.z, 0.0f);
    h1a.w = fmaxf(aca.w * inv + ska.w, 0.0f);
    h1b.x = fmaxf(acb.x * inv + skb.x, 0.0f);
    h1b.y = fmaxf(acb.y * inv + skb.y, 0.0f);
    h1b.z = fmaxf(acb.z * inv + skb.z, 0.0f);
    h1b.w = fmaxf(acb.w * inv + skb.w, 0.0f);

    // gemm2: half0 computes outputs j=0..7, half1 computes j=8..15
    int jbase = half * 8;
    float part[8];
#pragma unroll
    for (int jj = 0; jj < 8; jj++) {
        int jo = jbase + jj;
        float4 w0 = *(float4*)&Wsm[jo][l * 8];
        float4 w1 = *(float4*)&Wsm[jo][l * 8 + 4];
        float p = dot4(h1a, w0) + dot4(h1b, w1);
#pragma unroll
        for (int d = 8; d > 0; d >>= 1)
            p += __shfl_xor_sync(0xffffffffu, p, d, 16);
        part[jj] = p;
    }
    if (l == 0) {
        // output layout: [q(4) | kv interleaved(8) | s(4)]
        float* o = &g_QKVS2[n * 16];
        if (half == 0) {
#pragma unroll
            for (int c = 0; c < 4; c++) {
                o[c] = part[c] + bsm[c];
                o[4 + 2 * c] = part[4 + c] + bsm[4 + c];
            }
        } else {
#pragma unroll
            for (int c = 0; c < 4; c++) {
                o[5 + 2 * c] = part[c] + bsm[8 + c];
                o[12 + c]    = part[4 + c] + bsm[12 + c];
            }
        }
    }
}

// ---------------- layer-2 edge phase + final linear + mean (one kernel) ---
__global__ __launch_bounds__(256) void edge2_fused(
        const float* __restrict__ Wl, const float* __restrict__ bl,
        float* __restrict__ out) {
    __shared__ float ysm[8];
    int tid = threadIdx.x;
    int t = blockIdx.x * 256 + tid;
    int n = t >> 2, h = t & 3;

    float y = 0.0f;
    if (n < NN) {
        int off = g_off[n], end = g_off[n + 1];
        float qh = g_QKVS2[n * 16 + h];
        float s = 0.0f, a = 0.0f;
        int i = off;
        for (; i + 4 <= end; i += 4) {
            int s0 = g_ssrc[i], s1 = g_ssrc[i + 1], s2 = g_ssrc[i + 2], s3 = g_ssrc[i + 3];
            float2 kv0 = *(const float2*)&g_QKVS2[s0 * 16 + 4 + 2 * h];
            float2 kv1 = *(const float2*)&g_QKVS2[s1 * 16 + 4 + 2 * h];
            float2 kv2 = *(const float2*)&g_QKVS2[s2 * 16 + 4 + 2 * h];
            float2 kv3 = *(const float2*)&g_QKVS2[s3 * 16 + 4 + 2 * h];
            float e0 = __expf(qh * kv0.x);
            float e1 = __expf(qh * kv1.x);
            float e2 = __expf(qh * kv2.x);
            float e3 = __expf(qh * kv3.x);
            s += (e0 + e1) + (e2 + e3);
            a += e0 * kv0.y + e1 * kv1.y + e2 * kv2.y + e3 * kv3.y;
        }
        for (; i < end; i++) {
            int sn = g_ssrc[i];
            float2 kv = *(const float2*)&g_QKVS2[sn * 16 + 4 + 2 * h];
            float e = __expf(qh * kv.x);
            s += e;
            a += e * kv.y;
        }
        float o = a / (s + EPSV) + g_QKVS2[n * 16 + 12 + h];
        y = o * Wl[h];
    }

#pragma unroll
    for (int d = 16; d > 0; d >>= 1) y += __shfl_xor_sync(0xffffffffu, y, d);
    if ((tid & 31) == 0) ysm[tid >> 5] = y;
    __syncthreads();
    if (tid == 0) {
        float tsum = 0.f;
#pragma unroll
        for (int w = 0; w < 8; w++) tsum += ysm[w];
        atomicAdd(&g_accum, tsum);
        __threadfence();
        int ticket = atomicAdd(&g_done, 1);
        if (ticket == (int)gridDim.x - 1) {
            out[0] = g_accum * (1.0f / (float)NN) + bl[0];
        }
    }
}

// ---------------- launch --------------------------------------------------
extern "C" void kernel_launch(void* const* d_in, const int* in_sizes, int n_in,
                              void* d_out, int out_size) {
    const float* x    = (const float*)d_in[0];
    const int*   esrc = (const int*)d_in[1];
    const int*   edst = (const int*)d_in[2];
    const float* W1q = (const float*)d_in[3];  const float* b1q = (const float*)d_in[4];
    const float* W1k = (const float*)d_in[5];  const float* b1k = (const float*)d_in[6];
    const float* W1v = (const float*)d_in[7];  const float* b1v = (const float*)d_in[8];
    const float* W1s = (const float*)d_in[9];  const float* b1s = (const float*)d_in[10];
    const float* W2q = (const float*)d_in[11]; const float* b2q = (const float*)d_in[12];
    const float* W2k = (const float*)d_in[13]; const float* b2k = (const float*)d_in[14];
    const float* W2v = (const float*)d_in[15]; const float* b2v = (const float*)d_in[16];
    const float* W2s = (const float*)d_in[17]; const float* b2s = (const float*)d_in[18];
    const float* Wl  = (const float*)d_in[19]; const float* bl  = (const float*)d_in[20];
    float* out = (float*)d_out;

    // one-time creation of side stream + events (not device memory)
    static cudaStream_t sB = nullptr;
    static cudaEvent_t evFork = nullptr, evJoin = nullptr;
    if (!sB) {
        cudaStreamCreateWithFlags(&sB, cudaStreamNonBlocking);
        cudaEventCreateWithFlags(&evFork, cudaEventDisableTiming);
        cudaEventCreateWithFlags(&evJoin, cudaEventDisableTiming);
    }

    // fork: CSR build on sB, overlapped with gemm1 on the main stream
    cudaEventRecord(evFork, 0);
    cudaStreamWaitEvent(sB, evFork, 0);

    init_kernel<<<(NN + 255) / 256, 256, 0, sB>>>();
    hist_kernel<<<(EE / 4 + 255) / 256, 256, 0, sB>>>(edst);
    scan_kernel<<<1, 1024, 0, sB>>>();
    scatter_kernel<<<(EE / 4 + 255) / 256, 256, 0, sB>>>(esrc, edst);
    cudaEventRecord(evJoin, sB);

    dim3 g1((NN + 127) / 128, 4);
    gemm1_kernel<<<g1, 256>>>(x, W1q, b1q, W1k, b1k, W1v, b1v, W1s, b1s);

    // join: edge phase needs both gemm1 (main) and CSR (sB)
    cudaStreamWaitEvent(0, evJoin, 0);

    edge1_fused<<<NN / 8, 256>>>(W2q, b2q, W2k, b2k, W2v, b2v, W2s, b2s);
    edge2_fused<<<(NN * 4 + 255) / 256, 256>>>(Wl, bl, out);
}

// round 13
// speedup vs baseline: 1.1824x; 1.0281x over previous
#include <cuda_runtime.h>
#include <cuda_bf16.h>
#include <cstdint>
#include <math.h>
#include <float.h>

#define NN 20000
#define EE 320000
#define EPSV 1e-16f
#define SCALE1 0.17677669529663687f   // 1/sqrt(32)

// ---------------- device scratch (static; no cudaMalloc) ------------------
__device__ float g_QS1[NN * 256];     // per node: [q(128)|s(128)] fp32
__device__ __nv_bfloat16 g_KV16[NN * 256]; // per node: [k(128)|v(128)] bf16
__device__ float g_QKVS2[NN * 16];    // per node: [q(4)|kv interleaved(8)|s(4)]
__device__ int   g_deg[NN];
__device__ int   g_off[NN + 1];
__device__ int   g_pos[NN];
__device__ int   g_ssrc[EE];          // src sorted by dst (CSR payload)
__device__ float g_accum;
__device__ int   g_done;

// ---------------- f32x2 packed-FMA helpers --------------------------------
#define FMA2(d, a, b, c) \
    asm("fma.rn.f32x2 %0, %1, %2, %3;" : "=l"(d) : "l"(a), "l"(b), "l"(c))

__device__ __forceinline__ unsigned long long pack2(float lo, float hi) {
    unsigned long long o;
    asm("mov.b64 %0, {%1, %2};" : "=l"(o) : "r"(__float_as_uint(lo)), "r"(__float_as_uint(hi)));
    return o;
}
__device__ __forceinline__ float2 unpack2(unsigned long long v) {
    unsigned lo, hi;
    asm("mov.b64 {%0, %1}, %2;" : "=r"(lo), "=r"(hi) : "l"(v));
    return make_float2(__uint_as_float(lo), __uint_as_float(hi));
}
__device__ __forceinline__ float dot4(float4 a, float4 b) {
    return a.x * b.x + a.y * b.y + a.z * b.z + a.w * b.w;
}
// load 8 bf16 (16B) -> two float4
__device__ __forceinline__ void ld_bf8(const __nv_bfloat16* p, float4& a, float4& b) {
    uint4 r = *(const uint4*)p;
    float2 f0 = __bfloat1622float2(*(__nv_bfloat162*)&r.x);
    float2 f1 = __bfloat1622float2(*(__nv_bfloat162*)&r.y);
    float2 f2 = __bfloat1622float2(*(__nv_bfloat162*)&r.z);
    float2 f3 = __bfloat1622float2(*(__nv_bfloat162*)&r.w);
    a = make_float4(f0.x, f0.y, f1.x, f1.y);
    b = make_float4(f2.x, f2.y, f3.x, f3.y);
}

// ---------------- init ----------------------------------------------------
__global__ void init_kernel() {
    int i = blockIdx.x * blockDim.x + threadIdx.x;
    if (i < NN) g_deg[i] = 0;
    if (i == 0) { g_accum = 0.0f; g_done = 0; }
}

// ---------------- CSR build (4 edges/thread for MLP) ----------------------
__global__ void hist_kernel(const int* __restrict__ dst) {
    int t = blockIdx.x * blockDim.x + threadIdx.x;
    int e = t * 4;
    if (e < EE) {
        int4 d4 = *(const int4*)&dst[e];
        atomicAdd(&g_deg[d4.x], 1);
        atomicAdd(&g_deg[d4.y], 1);
        atomicAdd(&g_deg[d4.z], 1);
        atomicAdd(&g_deg[d4.w], 1);
    }
}

__global__ void scan_kernel() {
    __shared__ int wsum[32];
    __shared__ int carry_sh;
    int tid = threadIdx.x;
    int lane = tid & 31, wid = tid >> 5;
    if (tid == 0) { carry_sh = 0; g_off[0] = 0; }
    __syncthreads();

    const int CHUNKS = (NN + 1023) / 1024;
    for (int c = 0; c < CHUNKS; c++) {
        int i = c * 1024 + tid;
        int v = (i < NN) ? g_deg[i] : 0;
        int base = carry_sh;
        int incl = v;
#pragma unroll
        for (int d = 1; d < 32; d <<= 1) {
            int t = __shfl_up_sync(0xffffffffu, incl, d);
            if (lane >= d) incl += t;
        }
        if (lane == 31) wsum[wid] = incl;
        __syncthreads();
        if (wid == 0) {
            int wi = wsum[lane];
#pragma unroll
            for (int d = 1; d < 32; d <<= 1) {
                int t = __shfl_up_sync(0xffffffffu, wi, d);
                if (lane >= d) wi += t;
            }
            wsum[lane] = wi;
        }
        __syncthreads();
        int wexcl = (wid == 0) ? 0 : wsum[wid - 1];
        int total = wsum[31];
        int my_incl = base + wexcl + incl;
        if (i < NN) {
            g_off[i + 1] = my_incl;
            g_pos[i] = my_incl - v;
        }
        __syncthreads();
        if (tid == 0) carry_sh = base + total;
        __syncthreads();
    }
}

__global__ void scatter_kernel(const int* __restrict__ src, const int* __restrict__ dst) {
    int t = blockIdx.x * blockDim.x + threadIdx.x;
    int e = t * 4;
    if (e >= EE) return;
    int4 d4 = *(const int4*)&dst[e];
    int4 s4 = *(const int4*)&src[e];
    int p0 = atomicAdd(&g_pos[d4.x], 1);
    int p1 = atomicAdd(&g_pos[d4.y], 1);
    int p2 = atomicAdd(&g_pos[d4.z], 1);
    int p3 = atomicAdd(&g_pos[d4.w], 1);
    g_ssrc[p0] = s4.x;
    g_ssrc[p1] = s4.y;
    g_ssrc[p2] = s4.z;
    g_ssrc[p3] = s4.w;
}

// ---------------- layer-1 fused QKVS GEMM (f32x2, MOV-free inner loop) ----
// m=0 -> fp32 q in g_QS1[:,0:128]; m=3 -> fp32 s in g_QS1[:,128:256];
// m=1/2 -> bf16 k/v in g_KV16 ONLY (fp32 k/v stores were dead).
__global__ __launch_bounds__(256) void gemm1_kernel(
        const float* __restrict__ x,
        const float* __restrict__ Wq, const float* __restrict__ bq,
        const float* __restrict__ Wk, const float* __restrict__ bk,
        const float* __restrict__ Wv, const float* __restrict__ bv,
        const float* __restrict__ Ws, const float* __restrict__ bs) {
    __shared__ unsigned long long As2[16][128];   // (a,a) packed, [k][row]
    __shared__ float Bs[16][128];                 // [k][col]

    int tid = threadIdx.x;
    int tx = tid & 15;
    int ty = tid >> 4;
    int row0 = blockIdx.x * 128;
    int m = blockIdx.y;

    const float* W = (m == 0) ? Wq : (m == 1) ? Wk : (m == 2) ? Wv : Ws;
    const float* B = (m == 0) ? bq : (m == 1) ? bk : (m == 2) ? bv : bs;

    unsigned long long acc[8][4];
#pragma unroll
    for (int i = 0; i < 8; i++)
#pragma unroll
        for (int j = 0; j < 4; j++) acc[i][j] = 0ull;

    int arow = tid & 127;
    int akq  = (tid >> 7) * 8;
    int bcol = (tid & 31) * 4;
    int bkr  = tid >> 5;

    for (int kt = 0; kt < 8; kt++) {
        int k0 = kt * 16;
        int gr = row0 + arow;
        float4 xa = make_float4(0.f, 0.f, 0.f, 0.f);
        float4 xb = make_float4(0.f, 0.f, 0.f, 0.f);
        if (gr < NN) {
            xa = *(const float4*)&x[gr * 128 + k0 + akq];
            xb = *(const float4*)&x[gr * 128 + k0 + akq + 4];
        }
        As2[akq + 0][arow] = pack2(xa.x, xa.x);
        As2[akq + 1][arow] = pack2(xa.y, xa.y);
        As2[akq + 2][arow] = pack2(xa.z, xa.z);
        As2[akq + 3][arow] = pack2(xa.w, xa.w);
        As2[akq + 4][arow] = pack2(xb.x, xb.x);
        As2[akq + 5][arow] = pack2(xb.y, xb.y);
        As2[akq + 6][arow] = pack2(xb.z, xb.z);
        As2[akq + 7][arow] = pack2(xb.w, xb.w);
        *(float4*)&Bs[bkr][bcol]     = *(const float4*)&W[(k0 + bkr) * 128 + bcol];
        *(float4*)&Bs[bkr + 8][bcol] = *(const float4*)&W[(k0 + bkr + 8) * 128 + bcol];
        __syncthreads();

#pragma unroll
        for (int kk = 0; kk < 16; kk++) {
            ulonglong2 b01 = *(ulonglong2*)&Bs[kk][tx * 8];
            ulonglong2 b23 = *(ulonglong2*)&Bs[kk][tx * 8 + 4];
#pragma unroll
            for (int i = 0; i < 8; i++) {
                unsigned long long a = As2[kk][ty * 8 + i];
                FMA2(acc[i][0], a, b01.x, acc[i][0]);
                FMA2(acc[i][1], a, b01.y, acc[i][1]);
                FMA2(acc[i][2], a, b23.x, acc[i][2]);
                FMA2(acc[i][3], a, b23.y, acc[i][3]);
            }
        }
        __syncthreads();
    }

    float4 bb0 = *(const float4*)&B[tx * 8];
    float4 bb1 = *(const float4*)&B[tx * 8 + 4];
#pragma unroll
    for (int i = 0; i < 8; i++) {
        int gr = row0 + ty * 8 + i;
        if (gr < NN) {
            float2 p0 = unpack2(acc[i][0]);
            float2 p1 = unpack2(acc[i][1]);
            float2 p2 = unpack2(acc[i][2]);
            float2 p3 = unpack2(acc[i][3]);
            float4 o0 = make_float4(p0.x + bb0.x, p0.y + bb0.y, p1.x + bb0.z, p1.y + bb0.w);
            float4 o1 = make_float4(p2.x + bb1.x, p2.y + bb1.y, p3.x + bb1.z, p3.y + bb1.w);
            if (m == 0) {
                *(float4*)&g_QS1[gr * 256 + tx * 8]     = o0;
                *(float4*)&g_QS1[gr * 256 + tx * 8 + 4] = o1;
            } else if (m == 3) {
                *(float4*)&g_QS1[gr * 256 + 128 + tx * 8]     = o0;
                *(float4*)&g_QS1[gr * 256 + 128 + tx * 8 + 4] = o1;
            } else {
                __nv_bfloat162 hh[4];
                hh[0] = __floats2bfloat162_rn(o0.x, o0.y);
                hh[1] = __floats2bfloat162_rn(o0.z, o0.w);
                hh[2] = __floats2bfloat162_rn(o1.x, o1.y);
                hh[3] = __floats2bfloat162_rn(o1.z, o1.w);
                *(uint4*)&g_KV16[gr * 256 + (m - 1) * 128 + tx * 8] = *(uint4*)hh;
            }
        }
    }
}

// ---------------- layer-1 fused edge phase + gemm2 (single pass) ----------
// warp per dst node; 16 lanes per edge; bf16 k/v gathers (16B each).
__global__ __launch_bounds__(256) void edge1_fused(
        const float* __restrict__ W2q, const float* __restrict__ b2q,
        const float* __restrict__ W2k, const float* __restrict__ b2k,
        const float* __restrict__ W2v, const float* __restrict__ b2v,
        const float* __restrict__ W2s, const float* __restrict__ b2s) {
    __shared__ float Wsm[16][128];    // [out j][in i], j = m*4+c
    __shared__ float bsm[16];

    int tid = threadIdx.x;
    for (int f = tid; f < 2048; f += 256) {
        int j = f >> 7, i = f & 127;
        int mm = j >> 2, c = j & 3;
        const float* Wm = (mm == 0) ? W2q : (mm == 1) ? W2k : (mm == 2) ? W2v : W2s;
        Wsm[j][i] = Wm[i * 4 + c];
    }
    if (tid < 16) {
        int mm = tid >> 2, c = tid & 3;
        const float* bm = (mm == 0) ? b2q : (mm == 1) ? b2k : (mm == 2) ? b2v : b2s;
        bsm[tid] = bm[c];
    }
    __syncthreads();

    int wid = tid >> 5, lane = tid & 31;
    int half = lane >> 4;
    int l = lane & 15;
    int n = blockIdx.x * 8 + wid;

    int off = g_off[n];
    int deg = g_off[n + 1] - off;
    int steps = (deg + 1) >> 1;

    const float* base1 = &g_QS1[(size_t)n * 256 + l * 8];
    float4 qa = *(const float4*)(base1);
    float4 qb = *(const float4*)(base1 + 4);

    float se = 0.0f;
    float4 aca = make_float4(0.f, 0.f, 0.f, 0.f);
    float4 acb = make_float4(0.f, 0.f, 0.f, 0.f);

    int j = 0;
    for (; j + 2 <= steps; j += 2) {
        int i0 = 2 * j + half;
        int i1 = i0 + 2;
        bool ok0 = i0 < deg;
        bool ok1 = i1 < deg;
        int s0 = g_ssrc[off + (ok0 ? i0 : 0)];
        int s1 = g_ssrc[off + (ok1 ? i1 : 0)];
        const __nv_bfloat16* p0 = &g_KV16[(size_t)s0 * 256 + l * 8];
        const __nv_bfloat16* p1 = &g_KV16[(size_t)s1 * 256 + l * 8];
        float4 k0a, k0b, k1a, k1b, v0a, v0b, v1a, v1b;
        ld_bf8(p0, k0a, k0b);
        ld_bf8(p1, k1a, k1b);
        ld_bf8(p0 + 128, v0a, v0b);
        ld_bf8(p1 + 128, v1a, v1b);
        float d0 = dot4(qa, k0a) + dot4(qb, k0b);
        float d1 = dot4(qa, k1a) + dot4(qb, k1b);
        d0 += __shfl_xor_sync(0xffffffffu, d0, 1, 4);
        d1 += __shfl_xor_sync(0xffffffffu, d1, 1, 4);
        d0 += __shfl_xor_sync(0xffffffffu, d0, 2, 4);
        d1 += __shfl_xor_sync(0xffffffffu, d1, 2, 4);
        float e0 = ok0 ? __expf(d0 * SCALE1) : 0.0f;
        float e1 = ok1 ? __expf(d1 * SCALE1) : 0.0f;
        se += e0 + e1;
        aca.x += e0 * v0a.x + e1 * v1a.x;
        aca.y += e0 * v0a.y + e1 * v1a.y;
        aca.z += e0 * v0a.z + e1 * v1a.z;
        aca.w += e0 * v0a.w + e1 * v1a.w;
        acb.x += e0 * v0b.x + e1 * v1b.x;
        acb.y += e0 * v0b.y + e1 * v1b.y;
        acb.z += e0 * v0b.z + e1 * v1b.z;
        acb.w += e0 * v0b.w + e1 * v1b.w;
    }
    if (j < steps) {
        int i0 = 2 * j + half;
        bool ok0 = i0 < deg;
        int s = g_ssrc[off + (ok0 ? i0 : 0)];
        const __nv_bfloat16* p = &g_KV16[(size_t)s * 256 + l * 8];
        float4 ka, kb, va, vb;
        ld_bf8(p, ka, kb);
        ld_bf8(p + 128, va, vb);
        float d = dot4(qa, ka) + dot4(qb, kb);
        d += __shfl_xor_sync(0xffffffffu, d, 1, 4);
        d += __shfl_xor_sync(0xffffffffu, d, 2, 4);
        float e = ok0 ? __expf(d * SCALE1) : 0.0f;
        se += e;
        aca.x += e * va.x; aca.y += e * va.y; aca.z += e * va.z; aca.w += e * va.w;
        acb.x += e * vb.x; acb.y += e * vb.y; acb.z += e * vb.z; acb.w += e * vb.w;
    }

    // cross-half combine (halves processed disjoint edge sets)
    se += __shfl_xor_sync(0xffffffffu, se, 16);
    aca.x += __shfl_xor_sync(0xffffffffu, aca.x, 16);
    aca.y += __shfl_xor_sync(0xffffffffu, aca.y, 16);
    aca.z += __shfl_xor_sync(0xffffffffu, aca.z, 16);
    aca.w += __shfl_xor_sync(0xffffffffu, aca.w, 16);
    acb.x += __shfl_xor_sync(0xffffffffu, acb.x, 16);
    acb.y += __shfl_xor_sync(0xffffffffu, acb.y, 16);
    acb.z += __shfl_xor_sync(0xffffffffu, acb.z, 16);
    acb.w += __shfl_xor_sync(0xffffffffu, acb.w, 16);

    float inv = 1.0f / (se + EPSV);
    float4 ska = *(const float4*)(base1 + 128);
    float4 skb = *(const float4*)(base1 + 132);
    float4 h1a, h1b;
    h1a.x = fmaxf(aca.x * inv + ska.x, 0.0f);
    h1a.y = fmaxf(aca.y * inv + ska.y, 0.0f);
    h1a.z = fmaxf(aca.z * inv + ska.z, 0.0f);
    h1a.w = fmaxf(aca.w * inv + ska.w, 0.0f);
    h1b.x = fmaxf(acb.x * inv + skb.x, 0.0f);
    h1b.y = fmaxf(acb.y * inv + skb.y, 0.0f);
    h1b.z = fmaxf(acb.z * inv + skb.z, 0.0f);
    h1b.w = fmaxf(acb.w * inv + skb.w, 0.0f);

    // gemm2: half0 computes outputs j=0..7, half1 computes j=8..15
    int jbase = half * 8;
    float part[8];
#pragma unroll
    for (int jj = 0; jj < 8; jj++) {
        int jo = jbase + jj;
        float4 w0 = *(float4*)&Wsm[jo][l * 8];
        float4 w1 = *(float4*)&Wsm[jo][l * 8 + 4];
        float p = dot4(h1a, w0) + dot4(h1b, w1);
#pragma unroll
        for (int d = 8; d > 0; d >>= 1)
            p += __shfl_xor_sync(0xffffffffu, p, d, 16);
        part[jj] = p;
    }
    if (l == 0) {
        // output layout: [q(4) | kv interleaved(8) | s(4)]
        float* o = &g_QKVS2[n * 16];
        if (half == 0) {
#pragma unroll
            for (int c = 0; c < 4; c++) {
                o[c] = part[c] + bsm[c];
                o[4 + 2 * c] = part[4 + c] + bsm[4 + c];
            }
        } else {
#pragma unroll
            for (int c = 0; c < 4; c++) {
                o[5 + 2 * c] = part[c] + bsm[8 + c];
                o[12 + c]    = part[4 + c] + bsm[12 + c];
            }
        }
    }
}

// ---------------- layer-2 edge phase + final linear + mean (one kernel) ---
__global__ __launch_bounds__(256) void edge2_fused(
        const float* __restrict__ Wl, const float* __restrict__ bl,
        float* __restrict__ out) {
    __shared__ float ysm[8];
    int tid = threadIdx.x;
    int t = blockIdx.x * 256 + tid;
    int n = t >> 2, h = t & 3;

    float y = 0.0f;
    if (n < NN) {
        int off = g_off[n], end = g_off[n + 1];
        float qh = g_QKVS2[n * 16 + h];
        float s = 0.0f, a = 0.0f;
        int i = off;
        for (; i + 4 <= end; i += 4) {
            int s0 = g_ssrc[i], s1 = g_ssrc[i + 1], s2 = g_ssrc[i + 2], s3 = g_ssrc[i + 3];
            float2 kv0 = *(const float2*)&g_QKVS2[s0 * 16 + 4 + 2 * h];
            float2 kv1 = *(const float2*)&g_QKVS2[s1 * 16 + 4 + 2 * h];
            float2 kv2 = *(const float2*)&g_QKVS2[s2 * 16 + 4 + 2 * h];
            float2 kv3 = *(const float2*)&g_QKVS2[s3 * 16 + 4 + 2 * h];
            float e0 = __expf(qh * kv0.x);
            float e1 = __expf(qh * kv1.x);
            float e2 = __expf(qh * kv2.x);
            float e3 = __expf(qh * kv3.x);
            s += (e0 + e1) + (e2 + e3);
            a += e0 * kv0.y + e1 * kv1.y + e2 * kv2.y + e3 * kv3.y;
        }
        for (; i < end; i++) {
            int sn = g_ssrc[i];
            float2 kv = *(const float2*)&g_QKVS2[sn * 16 + 4 + 2 * h];
            float e = __expf(qh * kv.x);
            s += e;
            a += e * kv.y;
        }
        float o = a / (s + EPSV) + g_QKVS2[n * 16 + 12 + h];
        y = o * Wl[h];
    }

#pragma unroll
    for (int d = 16; d > 0; d >>= 1) y += __shfl_xor_sync(0xffffffffu, y, d);
    if ((tid & 31) == 0) ysm[tid >> 5] = y;
    __syncthreads();
    if (tid == 0) {
        float tsum = 0.f;
#pragma unroll
        for (int w = 0; w < 8; w++) tsum += ysm[w];
        atomicAdd(&g_accum, tsum);
        __threadfence();
        int ticket = atomicAdd(&g_done, 1);
        if (ticket == (int)gridDim.x - 1) {
            out[0] = g_accum * (1.0f / (float)NN) + bl[0];
        }
    }
}

// ---------------- launch --------------------------------------------------
extern "C" void kernel_launch(void* const* d_in, const int* in_sizes, int n_in,
                              void* d_out, int out_size) {
    const float* x    = (const float*)d_in[0];
    const int*   esrc = (const int*)d_in[1];
    const int*   edst = (const int*)d_in[2];
    const float* W1q = (const float*)d_in[3];  const float* b1q = (const float*)d_in[4];
    const float* W1k = (const float*)d_in[5];  const float* b1k = (const float*)d_in[6];
    const float* W1v = (const float*)d_in[7];  const float* b1v = (const float*)d_in[8];
    const float* W1s = (const float*)d_in[9];  const float* b1s = (const float*)d_in[10];
    const float* W2q = (const float*)d_in[11]; const float* b2q = (const float*)d_in[12];
    const float* W2k = (const float*)d_in[13]; const float* b2k = (const float*)d_in[14];
    const float* W2v = (const float*)d_in[15]; const float* b2v = (const float*)d_in[16];
    const float* W2s = (const float*)d_in[17]; const float* b2s = (const float*)d_in[18];
    const float* Wl  = (const float*)d_in[19]; const float* bl  = (const float*)d_in[20];
    float* out = (float*)d_out;

    // one-time creation of side stream + events (not device memory)
    static cudaStream_t sB = nullptr;
    static cudaEvent_t evFork = nullptr, evJoin = nullptr;
    if (!sB) {
        cudaStreamCreateWithFlags(&sB, cudaStreamNonBlocking);
        cudaEventCreateWithFlags(&evFork, cudaEventDisableTiming);
        cudaEventCreateWithFlags(&evJoin, cudaEventDisableTiming);
    }

    // fork: CSR build on sB, overlapped with gemm1 on the main stream
    cudaEventRecord(evFork, 0);
    cudaStreamWaitEvent(sB, evFork, 0);

    init_kernel<<<(NN + 255) / 256, 256, 0, sB>>>();
    hist_kernel<<<(EE / 4 + 255) / 256, 256, 0, sB>>>(edst);
    scan_kernel<<<1, 1024, 0, sB>>>();
    scatter_kernel<<<(EE / 4 + 255) / 256, 256, 0, sB>>>(esrc, edst);
    cudaEventRecord(evJoin, sB);

    dim3 g1((NN + 127) / 128, 4);
    gemm1_kernel<<<g1, 256>>>(x, W1q, b1q, W1k, b1k, W1v, b1v, W1s, b1s);

    // join: edge phase needs both gemm1 (main) and CSR (sB)
    cudaStreamWaitEvent(0, evJoin, 0);

    edge1_fused<<<NN / 8, 256>>>(W2q, b2q, W2k, b2k, W2v, b2v, W2s, b2s);
    edge2_fused<<<(NN * 4 + 255) / 256, 256>>>(Wl, bl, out);
}

// round 14
// speedup vs baseline: 1.1829x; 1.0004x over previous
#include <cuda_runtime.h>
#include <cuda_bf16.h>
#include <cstdint>
#include <math.h>
#include <float.h>

#define NN 20000
#define EE 320000
#define EPSV 1e-16f
#define SCALE1 0.17677669529663687f   // 1/sqrt(32)
#define IDX_CAP 64

// ---------------- device scratch (static; no cudaMalloc) ------------------
__device__ float g_QS1[NN * 256];     // per node: [q(128)|s(128)] fp32
__device__ __nv_bfloat16 g_KV16[NN * 256]; // per node: [k(128)|v(128)] bf16
__device__ float g_QKVS2[NN * 16];    // per node: [q(4)|kv interleaved(8)|s(4)]
__device__ int   g_deg[NN];
__device__ int   g_off[NN + 1];
__device__ int   g_pos[NN];
__device__ int   g_ssrc[EE];          // src sorted by dst (CSR payload)
__device__ float g_accum;
__device__ int   g_done;

// ---------------- f32x2 packed-FMA helpers --------------------------------
#define FMA2(d, a, b, c) \
    asm("fma.rn.f32x2 %0, %1, %2, %3;" : "=l"(d) : "l"(a), "l"(b), "l"(c))

__device__ __forceinline__ unsigned long long pack2(float lo, float hi) {
    unsigned long long o;
    asm("mov.b64 %0, {%1, %2};" : "=l"(o) : "r"(__float_as_uint(lo)), "r"(__float_as_uint(hi)));
    return o;
}
__device__ __forceinline__ float2 unpack2(unsigned long long v) {
    unsigned lo, hi;
    asm("mov.b64 {%0, %1}, %2;" : "=r"(lo), "=r"(hi) : "l"(v));
    return make_float2(__uint_as_float(lo), __uint_as_float(hi));
}
__device__ __forceinline__ float dot4(float4 a, float4 b) {
    return a.x * b.x + a.y * b.y + a.z * b.z + a.w * b.w;
}
// load 8 bf16 (16B) -> two float4
__device__ __forceinline__ void ld_bf8(const __nv_bfloat16* p, float4& a, float4& b) {
    uint4 r = *(const uint4*)p;
    float2 f0 = __bfloat1622float2(*(__nv_bfloat162*)&r.x);
    float2 f1 = __bfloat1622float2(*(__nv_bfloat162*)&r.y);
    float2 f2 = __bfloat1622float2(*(__nv_bfloat162*)&r.z);
    float2 f3 = __bfloat1622float2(*(__nv_bfloat162*)&r.w);
    a = make_float4(f0.x, f0.y, f1.x, f1.y);
    b = make_float4(f2.x, f2.y, f3.x, f3.y);
}

// ---------------- init ----------------------------------------------------
__global__ void init_kernel() {
    int i = blockIdx.x * blockDim.x + threadIdx.x;
    if (i < NN) g_deg[i] = 0;
    if (i == 0) { g_accum = 0.0f; g_done = 0; }
}

// ---------------- CSR build (4 edges/thread for MLP) ----------------------
__global__ void hist_kernel(const int* __restrict__ dst) {
    int t = blockIdx.x * blockDim.x + threadIdx.x;
    int e = t * 4;
    if (e < EE) {
        int4 d4 = *(const int4*)&dst[e];
        atomicAdd(&g_deg[d4.x], 1);
        atomicAdd(&g_deg[d4.y], 1);
        atomicAdd(&g_deg[d4.z], 1);
        atomicAdd(&g_deg[d4.w], 1);
    }
}

__global__ void scan_kernel() {
    __shared__ int wsum[32];
    __shared__ int carry_sh;
    int tid = threadIdx.x;
    int lane = tid & 31, wid = tid >> 5;
    if (tid == 0) { carry_sh = 0; g_off[0] = 0; }
    __syncthreads();

    const int CHUNKS = (NN + 1023) / 1024;
    for (int c = 0; c < CHUNKS; c++) {
        int i = c * 1024 + tid;
        int v = (i < NN) ? g_deg[i] : 0;
        int base = carry_sh;
        int incl = v;
#pragma unroll
        for (int d = 1; d < 32; d <<= 1) {
            int t = __shfl_up_sync(0xffffffffu, incl, d);
            if (lane >= d) incl += t;
        }
        if (lane == 31) wsum[wid] = incl;
        __syncthreads();
        if (wid == 0) {
            int wi = wsum[lane];
#pragma unroll
            for (int d = 1; d < 32; d <<= 1) {
                int t = __shfl_up_sync(0xffffffffu, wi, d);
                if (lane >= d) wi += t;
            }
            wsum[lane] = wi;
        }
        __syncthreads();
        int wexcl = (wid == 0) ? 0 : wsum[wid - 1];
        int total = wsum[31];
        int my_incl = base + wexcl + incl;
        if (i < NN) {
            g_off[i + 1] = my_incl;
            g_pos[i] = my_incl - v;
        }
        __syncthreads();
        if (tid == 0) carry_sh = base + total;
        __syncthreads();
    }
}

__global__ void scatter_kernel(const int* __restrict__ src, const int* __restrict__ dst) {
    int t = blockIdx.x * blockDim.x + threadIdx.x;
    int e = t * 4;
    if (e >= EE) return;
    int4 d4 = *(const int4*)&dst[e];
    int4 s4 = *(const int4*)&src[e];
    int p0 = atomicAdd(&g_pos[d4.x], 1);
    int p1 = atomicAdd(&g_pos[d4.y], 1);
    int p2 = atomicAdd(&g_pos[d4.z], 1);
    int p3 = atomicAdd(&g_pos[d4.w], 1);
    g_ssrc[p0] = s4.x;
    g_ssrc[p1] = s4.y;
    g_ssrc[p2] = s4.z;
    g_ssrc[p3] = s4.w;
}

// ---------------- layer-1 fused QKVS GEMM (f32x2, MOV-free inner loop) ----
// m=0 -> fp32 q in g_QS1[:,0:128]; m=3 -> fp32 s in g_QS1[:,128:256];
// m=1/2 -> bf16 k/v in g_KV16 ONLY.
__global__ __launch_bounds__(256) void gemm1_kernel(
        const float* __restrict__ x,
        const float* __restrict__ Wq, const float* __restrict__ bq,
        const float* __restrict__ Wk, const float* __restrict__ bk,
        const float* __restrict__ Wv, const float* __restrict__ bv,
        const float* __restrict__ Ws, const float* __restrict__ bs) {
    __shared__ unsigned long long As2[16][128];   // (a,a) packed, [k][row]
    __shared__ float Bs[16][128];                 // [k][col]

    int tid = threadIdx.x;
    int tx = tid & 15;
    int ty = tid >> 4;
    int row0 = blockIdx.x * 128;
    int m = blockIdx.y;

    const float* W = (m == 0) ? Wq : (m == 1) ? Wk : (m == 2) ? Wv : Ws;
    const float* B = (m == 0) ? bq : (m == 1) ? bk : (m == 2) ? bv : bs;

    unsigned long long acc[8][4];
#pragma unroll
    for (int i = 0; i < 8; i++)
#pragma unroll
        for (int j = 0; j < 4; j++) acc[i][j] = 0ull;

    int arow = tid & 127;
    int akq  = (tid >> 7) * 8;
    int bcol = (tid & 31) * 4;
    int bkr  = tid >> 5;

    for (int kt = 0; kt < 8; kt++) {
        int k0 = kt * 16;
        int gr = row0 + arow;
        float4 xa = make_float4(0.f, 0.f, 0.f, 0.f);
        float4 xb = make_float4(0.f, 0.f, 0.f, 0.f);
        if (gr < NN) {
            xa = *(const float4*)&x[gr * 128 + k0 + akq];
            xb = *(const float4*)&x[gr * 128 + k0 + akq + 4];
        }
        As2[akq + 0][arow] = pack2(xa.x, xa.x);
        As2[akq + 1][arow] = pack2(xa.y, xa.y);
        As2[akq + 2][arow] = pack2(xa.z, xa.z);
        As2[akq + 3][arow] = pack2(xa.w, xa.w);
        As2[akq + 4][arow] = pack2(xb.x, xb.x);
        As2[akq + 5][arow] = pack2(xb.y, xb.y);
        As2[akq + 6][arow] = pack2(xb.z, xb.z);
        As2[akq + 7][arow] = pack2(xb.w, xb.w);
        *(float4*)&Bs[bkr][bcol]     = *(const float4*)&W[(k0 + bkr) * 128 + bcol];
        *(float4*)&Bs[bkr + 8][bcol] = *(const float4*)&W[(k0 + bkr + 8) * 128 + bcol];
        __syncthreads();

#pragma unroll
        for (int kk = 0; kk < 16; kk++) {
            ulonglong2 b01 = *(ulonglong2*)&Bs[kk][tx * 8];
            ulonglong2 b23 = *(ulonglong2*)&Bs[kk][tx * 8 + 4];
#pragma unroll
            for (int i = 0; i < 8; i++) {
                unsigned long long a = As2[kk][ty * 8 + i];
                FMA2(acc[i][0], a, b01.x, acc[i][0]);
                FMA2(acc[i][1], a, b01.y, acc[i][1]);
                FMA2(acc[i][2], a, b23.x, acc[i][2]);
                FMA2(acc[i][3], a, b23.y, acc[i][3]);
            }
        }
        __syncthreads();
    }

    float4 bb0 = *(const float4*)&B[tx * 8];
    float4 bb1 = *(const float4*)&B[tx * 8 + 4];
#pragma unroll
    for (int i = 0; i < 8; i++) {
        int gr = row0 + ty * 8 + i;
        if (gr < NN) {
            float2 p0 = unpack2(acc[i][0]);
            float2 p1 = unpack2(acc[i][1]);
            float2 p2 = unpack2(acc[i][2]);
            float2 p3 = unpack2(acc[i][3]);
            float4 o0 = make_float4(p0.x + bb0.x, p0.y + bb0.y, p1.x + bb0.z, p1.y + bb0.w);
            float4 o1 = make_float4(p2.x + bb1.x, p2.y + bb1.y, p3.x + bb1.z, p3.y + bb1.w);
            if (m == 0) {
                *(float4*)&g_QS1[gr * 256 + tx * 8]     = o0;
                *(float4*)&g_QS1[gr * 256 + tx * 8 + 4] = o1;
            } else if (m == 3) {
                *(float4*)&g_QS1[gr * 256 + 128 + tx * 8]     = o0;
                *(float4*)&g_QS1[gr * 256 + 128 + tx * 8 + 4] = o1;
            } else {
                __nv_bfloat162 hh[4];
                hh[0] = __floats2bfloat162_rn(o0.x, o0.y);
                hh[1] = __floats2bfloat162_rn(o0.z, o0.w);
                hh[2] = __floats2bfloat162_rn(o1.x, o1.y);
                hh[3] = __floats2bfloat162_rn(o1.z, o1.w);
                *(uint4*)&g_KV16[gr * 256 + (m - 1) * 128 + tx * 8] = *(uint4*)hh;
            }
        }
    }
}

// ---------------- layer-1 fused edge phase + gemm2 (single pass) ----------
// warp per dst node; 16 lanes per edge; bf16 k/v gathers; edge indices
// staged in SMEM to break the index->gather L2 dependency chain.
__global__ __launch_bounds__(256) void edge1_fused(
        const float* __restrict__ W2q, const float* __restrict__ b2q,
        const float* __restrict__ W2k, const float* __restrict__ b2k,
        const float* __restrict__ W2v, const float* __restrict__ b2v,
        const float* __restrict__ W2s, const float* __restrict__ b2s) {
    __shared__ float Wsm[16][128];    // [out j][in i], j = m*4+c
    __shared__ float bsm[16];
    __shared__ int sidx[8][IDX_CAP];

    int tid = threadIdx.x;
    for (int f = tid; f < 2048; f += 256) {
        int j = f >> 7, i = f & 127;
        int mm = j >> 2, c = j & 3;
        const float* Wm = (mm == 0) ? W2q : (mm == 1) ? W2k : (mm == 2) ? W2v : W2s;
        Wsm[j][i] = Wm[i * 4 + c];
    }
    if (tid < 16) {
        int mm = tid >> 2, c = tid & 3;
        const float* bm = (mm == 0) ? b2q : (mm == 1) ? b2k : (mm == 2) ? b2v : b2s;
        bsm[tid] = bm[c];
    }
    __syncthreads();

    int wid = tid >> 5, lane = tid & 31;
    int half = lane >> 4;
    int l = lane & 15;
    int n = blockIdx.x * 8 + wid;

    int off = g_off[n];
    int deg = g_off[n + 1] - off;
    int steps = (deg + 1) >> 1;

    // stage indices into smem (coalesced, 2 iterations max for deg<=64)
    int ncap = (deg < IDX_CAP) ? deg : IDX_CAP;
    for (int i = lane; i < ncap; i += 32)
        sidx[wid][i] = g_ssrc[off + i];
    __syncwarp();

    const float* base1 = &g_QS1[(size_t)n * 256 + l * 8];
    float4 qa = *(const float4*)(base1);
    float4 qb = *(const float4*)(base1 + 4);

    float se = 0.0f;
    float4 aca = make_float4(0.f, 0.f, 0.f, 0.f);
    float4 acb = make_float4(0.f, 0.f, 0.f, 0.f);

    int j = 0;
    for (; j + 2 <= steps; j += 2) {
        int i0 = 2 * j + half;
        int i1 = i0 + 2;
        bool ok0 = i0 < deg;
        bool ok1 = i1 < deg;
        int ci0 = ok0 ? i0 : 0;
        int ci1 = ok1 ? i1 : 0;
        int s0 = (ci0 < IDX_CAP) ? sidx[wid][ci0] : g_ssrc[off + ci0];
        int s1 = (ci1 < IDX_CAP) ? sidx[wid][ci1] : g_ssrc[off + ci1];
        const __nv_bfloat16* p0 = &g_KV16[(size_t)s0 * 256 + l * 8];
        const __nv_bfloat16* p1 = &g_KV16[(size_t)s1 * 256 + l * 8];
        float4 k0a, k0b, k1a, k1b, v0a, v0b, v1a, v1b;
        ld_bf8(p0, k0a, k0b);
        ld_bf8(p1, k1a, k1b);
        ld_bf8(p0 + 128, v0a, v0b);
        ld_bf8(p1 + 128, v1a, v1b);
        float d0 = dot4(qa, k0a) + dot4(qb, k0b);
        float d1 = dot4(qa, k1a) + dot4(qb, k1b);
        d0 += __shfl_xor_sync(0xffffffffu, d0, 1, 4);
        d1 += __shfl_xor_sync(0xffffffffu, d1, 1, 4);
        d0 += __shfl_xor_sync(0xffffffffu, d0, 2, 4);
        d1 += __shfl_xor_sync(0xffffffffu, d1, 2, 4);
        float e0 = ok0 ? __expf(d0 * SCALE1) : 0.0f;
        float e1 = ok1 ? __expf(d1 * SCALE1) : 0.0f;
        se += e0 + e1;
        aca.x += e0 * v0a.x + e1 * v1a.x;
        aca.y += e0 * v0a.y + e1 * v1a.y;
        aca.z += e0 * v0a.z + e1 * v1a.z;
        aca.w += e0 * v0a.w + e1 * v1a.w;
        acb.x += e0 * v0b.x + e1 * v1b.x;
        acb.y += e0 * v0b.y + e1 * v1b.y;
        acb.z += e0 * v0b.z + e1 * v1b.z;
        acb.w += e0 * v0b.w + e1 * v1b.w;
    }
    if (j < steps) {
        int i0 = 2 * j + half;
        bool ok0 = i0 < deg;
        int ci0 = ok0 ? i0 : 0;
        int s = (ci0 < IDX_CAP) ? sidx[wid][ci0] : g_ssrc[off + ci0];
        const __nv_bfloat16* p = &g_KV16[(size_t)s * 256 + l * 8];
        float4 ka, kb, va, vb;
        ld_bf8(p, ka, kb);
        ld_bf8(p + 128, va, vb);
        float d = dot4(qa, ka) + dot4(qb, kb);
        d += __shfl_xor_sync(0xffffffffu, d, 1, 4);
        d += __shfl_xor_sync(0xffffffffu, d, 2, 4);
        float e = ok0 ? __expf(d * SCALE1) : 0.0f;
        se += e;
        aca.x += e * va.x; aca.y += e * va.y; aca.z += e * va.z; aca.w += e * va.w;
        acb.x += e * vb.x; acb.y += e * vb.y; acb.z += e * vb.z; acb.w += e * vb.w;
    }

    // cross-half combine (halves processed disjoint edge sets)
    se += __shfl_xor_sync(0xffffffffu, se, 16);
    aca.x += __shfl_xor_sync(0xffffffffu, aca.x, 16);
    aca.y += __shfl_xor_sync(0xffffffffu, aca.y, 16);
    aca.z += __shfl_xor_sync(0xffffffffu, aca.z, 16);
    aca.w += __shfl_xor_sync(0xffffffffu, aca.w, 16);
    acb.x += __shfl_xor_sync(0xffffffffu, acb.x, 16);
    acb.y += __shfl_xor_sync(0xffffffffu, acb.y, 16);
    acb.z += __shfl_xor_sync(0xffffffffu, acb.z, 16);
    acb.w += __shfl_xor_sync(0xffffffffu, acb.w, 16);

    float inv = 1.0f / (se + EPSV);
    float4 ska = *(const float4*)(base1 + 128);
    float4 skb = *(const float4*)(base1 + 132);
    float4 h1a, h1b;
    h1a.x = fmaxf(aca.x * inv + ska.x, 0.0f);
    h1a.y = fmaxf(aca.y * inv + ska.y, 0.0f);
    h1a.z = fmaxf(aca.z * inv + ska.z, 0.0f);
    h1a.w = fmaxf(aca.w * inv + ska.w, 0.0f);
    h1b.x = fmaxf(acb.x * inv + skb.x, 0.0f);
    h1b.y = fmaxf(acb.y * inv + skb.y, 0.0f);
    h1b.z = fmaxf(acb.z * inv + skb.z, 0.0f);
    h1b.w = fmaxf(acb.w * inv + skb.w, 0.0f);

    // gemm2: half0 computes outputs j=0..7, half1 computes j=8..15
    int jbase = half * 8;
    float part[8];
#pragma unroll
    for (int jj = 0; jj < 8; jj++) {
        int jo = jbase + jj;
        float4 w0 = *(float4*)&Wsm[jo][l * 8];
        float4 w1 = *(float4*)&Wsm[jo][l * 8 + 4];
        float p = dot4(h1a, w0) + dot4(h1b, w1);
#pragma unroll
        for (int d = 8; d > 0; d >>= 1)
            p += __shfl_xor_sync(0xffffffffu, p, d, 16);
        part[jj] = p;
    }
    if (l == 0) {
        // output layout: [q(4) | kv interleaved(8) | s(4)]
        float* o = &g_QKVS2[n * 16];
        if (half == 0) {
#pragma unroll
            for (int c = 0; c < 4; c++) {
                o[c] = part[c] + bsm[c];
                o[4 + 2 * c] = part[4 + c] + bsm[4 + c];
            }
        } else {
#pragma unroll
            for (int c = 0; c < 4; c++) {
                o[5 + 2 * c] = part[c] + bsm[8 + c];
                o[12 + c]    = part[4 + c] + bsm[12 + c];
            }
        }
    }
}

// ---------------- layer-2 edge phase + final linear + mean (one kernel) ---
__global__ __launch_bounds__(256) void edge2_fused(
        const float* __restrict__ Wl, const float* __restrict__ bl,
        float* __restrict__ out) {
    __shared__ float ysm[8];
    int tid = threadIdx.x;
    int t = blockIdx.x * 256 + tid;
    int n = t >> 2, h = t & 3;

    float y = 0.0f;
    if (n < NN) {
        int off = g_off[n], end = g_off[n + 1];
        float qh = g_QKVS2[n * 16 + h];
        float s = 0.0f, a = 0.0f;
        int i = off;
        for (; i + 4 <= end; i += 4) {
            int s0 = g_ssrc[i], s1 = g_ssrc[i + 1], s2 = g_ssrc[i + 2], s3 = g_ssrc[i + 3];
            float2 kv0 = *(const float2*)&g_QKVS2[s0 * 16 + 4 + 2 * h];
            float2 kv1 = *(const float2*)&g_QKVS2[s1 * 16 + 4 + 2 * h];
            float2 kv2 = *(const float2*)&g_QKVS2[s2 * 16 + 4 + 2 * h];
            float2 kv3 = *(const float2*)&g_QKVS2[s3 * 16 + 4 + 2 * h];
            float e0 = __expf(qh * kv0.x);
            float e1 = __expf(qh * kv1.x);
            float e2 = __expf(qh * kv2.x);
            float e3 = __expf(qh * kv3.x);
            s += (e0 + e1) + (e2 + e3);
            a += e0 * kv0.y + e1 * kv1.y + e2 * kv2.y + e3 * kv3.y;
        }
        for (; i < end; i++) {
            int sn = g_ssrc[i];
            float2 kv = *(const float2*)&g_QKVS2[sn * 16 + 4 + 2 * h];
            float e = __expf(qh * kv.x);
            s += e;
            a += e * kv.y;
        }
        float o = a / (s + EPSV) + g_QKVS2[n * 16 + 12 + h];
        y = o * Wl[h];
    }

#pragma unroll
    for (int d = 16; d > 0; d >>= 1) y += __shfl_xor_sync(0xffffffffu, y, d);
    if ((tid & 31) == 0) ysm[tid >> 5] = y;
    __syncthreads();
    if (tid == 0) {
        float tsum = 0.f;
#pragma unroll
        for (int w = 0; w < 8; w++) tsum += ysm[w];
        atomicAdd(&g_accum, tsum);
        __threadfence();
        int ticket = atomicAdd(&g_done, 1);
        if (ticket == (int)gridDim.x - 1) {
            out[0] = g_accum * (1.0f / (float)NN) + bl[0];
        }
    }
}

// ---------------- launch --------------------------------------------------
extern "C" void kernel_launch(void* const* d_in, const int* in_sizes, int n_in,
                              void* d_out, int out_size) {
    const float* x    = (const float*)d_in[0];
    const int*   esrc = (const int*)d_in[1];
    const int*   edst = (const int*)d_in[2];
    const float* W1q = (const float*)d_in[3];  const float* b1q = (const float*)d_in[4];
    const float* W1k = (const float*)d_in[5];  const float* b1k = (const float*)d_in[6];
    const float* W1v = (const float*)d_in[7];  const float* b1v = (const float*)d_in[8];
    const float* W1s = (const float*)d_in[9];  const float* b1s = (const float*)d_in[10];
    const float* W2q = (const float*)d_in[11]; const float* b2q = (const float*)d_in[12];
    const float* W2k = (const float*)d_in[13]; const float* b2k = (const float*)d_in[14];
    const float* W2v = (const float*)d_in[15]; const float* b2v = (const float*)d_in[16];
    const float* W2s = (const float*)d_in[17]; const float* b2s = (const float*)d_in[18];
    const float* Wl  = (const float*)d_in[19]; const float* bl  = (const float*)d_in[20];
    float* out = (float*)d_out;

    // one-time creation of side stream + events (not device memory)
    static cudaStream_t sB = nullptr;
    static cudaEvent_t evFork = nullptr, evJoin = nullptr;
    if (!sB) {
        cudaStreamCreateWithFlags(&sB, cudaStreamNonBlocking);
        cudaEventCreateWithFlags(&evFork, cudaEventDisableTiming);
        cudaEventCreateWithFlags(&evJoin, cudaEventDisableTiming);
    }

    // fork: CSR build on sB, overlapped with gemm1 on the main stream
    cudaEventRecord(evFork, 0);
    cudaStreamWaitEvent(sB, evFork, 0);

    init_kernel<<<(NN + 255) / 256, 256, 0, sB>>>();
    hist_kernel<<<(EE / 4 + 255) / 256, 256, 0, sB>>>(edst);
    scan_kernel<<<1, 1024, 0, sB>>>();
    scatter_kernel<<<(EE / 4 + 255) / 256, 256, 0, sB>>>(esrc, edst);
    cudaEventRecord(evJoin, sB);

    dim3 g1((NN + 127) / 128, 4);
    gemm1_kernel<<<g1, 256>>>(x, W1q, b1q, W1k, b1k, W1v, b1v, W1s, b1s);

    // join: edge phase needs both gemm1 (main) and CSR (sB)
    cudaStreamWaitEvent(0, evJoin, 0);

    edge1_fused<<<NN / 8, 256>>>(W2q, b2q, W2k, b2k, W2v, b2v, W2s, b2s);
    edge2_fused<<<(NN * 4 + 255) / 256, 256>>>(Wl, bl, out);
}